// round 5
// baseline (speedup 1.0000x reference)
#include <cuda_runtime.h>
#include <stdint.h>

// Problem constants (fixed by the reference)
#define B_     8192
#define W0_    1024
#define R_     8
#define G_     1024
#define WORDS  (B_ / 32)          // 256 batch words
#define OUTW   (W0_ + R_ * G_)    // 9216 output columns

// Bit matrix scratch: bits[col * WORDS + word]; bit l of word w = sample (w*32+l).
// 9216 * 256 * 4B = 9.4 MB — static device global (no allocation).
__device__ uint32_t g_bits[OUTW * WORDS];

// ---------------------------------------------------------------------------
// Pack: x [B, W0] 0/1 floats -> bit matrix for the first W0 columns.
// One block per batch word (32 samples). 8 warps; warp j covers cols [j*128, j*128+128).
// Lane l streams sequentially through row (w*32+l): per-lane float4 loads are
// contiguous, so the 32 distinct 128B lines per warp-load get 8x L1 reuse.
// ---------------------------------------------------------------------------
__global__ void pack_kernel(const float* __restrict__ x) {
    const int w    = blockIdx.x;           // batch word
    const int warp = threadIdx.x >> 5;
    const int lane = threadIdx.x & 31;
    const int b    = w * 32 + lane;
    const float4* row = reinterpret_cast<const float4*>(x + (size_t)b * W0_);
    const int colbase = warp * 128;

    #pragma unroll 4
    for (int it = 0; it < 32; ++it) {
        const int c = colbase + it * 4;
        float4 v = row[c >> 2];
        uint32_t b0 = __ballot_sync(0xffffffffu, v.x > 0.5f);
        uint32_t b1 = __ballot_sync(0xffffffffu, v.y > 0.5f);
        uint32_t b2 = __ballot_sync(0xffffffffu, v.z > 0.5f);
        uint32_t b3 = __ballot_sync(0xffffffffu, v.w > 0.5f);
        if (lane == 0) {
            g_bits[(c + 0) * WORDS + w] = b0;
            g_bits[(c + 1) * WORDS + w] = b1;
            g_bits[(c + 2) * WORDS + w] = b2;
            g_bits[(c + 3) * WORDS + w] = b3;
        }
    }
}

// ---------------------------------------------------------------------------
// One gate row: for each gate g, out_col = outbase + g.
//   a = bits[ca], b = bits[cb], out = LUT_{tt}(a, b) bitwise on 32 samples.
// Thread = one batch word; block handles 4 gates (coalesced 1KB column
// loads/stores; choices/gates are warp-uniform loads). Grid = G/4 blocks.
// All traffic is L2-resident (9.4 MB working set).
// ---------------------------------------------------------------------------
__global__ void row_kernel(const float* __restrict__ gates_r,   // [G,4]
                           const int*   __restrict__ choices_r, // [G,2]
                           int outbase) {
    const int w  = threadIdx.x;            // 0..255 batch word
    const int g0 = blockIdx.x * 4;

    #pragma unroll
    for (int k = 0; k < 4; ++k) {
        const int g  = g0 + k;
        const int ca = __ldg(choices_r + 2 * g + 0);
        const int cb = __ldg(choices_r + 2 * g + 1);
        const float4 tt = __ldg(reinterpret_cast<const float4*>(gates_r + 4 * g));

        const uint32_t a  = g_bits[(size_t)ca * WORDS + w];
        const uint32_t bb = g_bits[(size_t)cb * WORDS + w];

        const uint32_t m0 = (tt.x > 0.5f) ? 0xffffffffu : 0u;  // (a=0,b=0)
        const uint32_t m1 = (tt.y > 0.5f) ? 0xffffffffu : 0u;  // (a=0,b=1)
        const uint32_t m2 = (tt.z > 0.5f) ? 0xffffffffu : 0u;  // (a=1,b=0)
        const uint32_t m3 = (tt.w > 0.5f) ? 0xffffffffu : 0u;  // (a=1,b=1)

        const uint32_t o = (m0 & ~a & ~bb) | (m1 & ~a & bb)
                         | (m2 &  a & ~bb) | (m3 &  a &  bb);

        g_bits[(size_t)(outbase + g) * WORDS + w] = o;
    }
}

// ---------------------------------------------------------------------------
// Unpack: bit matrix -> out [B, OUTW] float32 (includes the original x columns,
// exact roundtrip since x is exactly 0/1). Thread owns 4 consecutive columns at
// one batch word: 4 word loads, then 32 coalesced float4 streaming stores
// (write-once output -> __stcs to limit L2 pollution of the 302 MB stream).
// Grid: (OUTW/1024, WORDS), block 256.
// ---------------------------------------------------------------------------
__global__ void unpack_kernel(float* __restrict__ out) {
    const int w  = blockIdx.y;                         // batch word
    const int c0 = blockIdx.x * 1024 + threadIdx.x * 4; // first of 4 columns

    const uint32_t b0 = g_bits[(size_t)(c0 + 0) * WORDS + w];
    const uint32_t b1 = g_bits[(size_t)(c0 + 1) * WORDS + w];
    const uint32_t b2 = g_bits[(size_t)(c0 + 2) * WORDS + w];
    const uint32_t b3 = g_bits[(size_t)(c0 + 3) * WORDS + w];

    float* base = out + (size_t)(w * 32) * OUTW + c0;

    #pragma unroll
    for (int i = 0; i < 32; ++i) {
        float4 v;
        v.x = (float)((b0 >> i) & 1u);
        v.y = (float)((b1 >> i) & 1u);
        v.z = (float)((b2 >> i) & 1u);
        v.w = (float)((b3 >> i) & 1u);
        __stcs(reinterpret_cast<float4*>(base + (size_t)i * OUTW), v);
    }
}

// ---------------------------------------------------------------------------
// Launch: pack -> 8 dependent row kernels -> unpack. All async on the default
// stream; no allocation, no sync -> graph-capturable.
// Inputs (metadata order): x f32 [8192,1024], gates f32 [8,1024,4],
// choices i32 [8,1024,2]. Output f32 [8192, 9216].
// ---------------------------------------------------------------------------
extern "C" void kernel_launch(void* const* d_in, const int* in_sizes, int n_in,
                              void* d_out, int out_size) {
    const float* x       = (const float*)d_in[0];
    const float* gates   = (const float*)d_in[1];
    const int*   choices = (const int*)  d_in[2];
    float*       out     = (float*)d_out;

    pack_kernel<<<WORDS, 256>>>(x);

    for (int r = 0; r < R_; ++r) {
        row_kernel<<<G_ / 4, 256>>>(gates + (size_t)r * G_ * 4,
                                    choices + (size_t)r * G_ * 2,
                                    W0_ + r * G_);
    }

    dim3 ugrid(OUTW / 1024, WORDS);
    unpack_kernel<<<ugrid, 256>>>(out);
}

// round 6
// speedup vs baseline: 1.2982x; 1.2982x over previous
#include <cuda_runtime.h>
#include <stdint.h>

// Problem constants (fixed by the reference)
#define B_     8192
#define W0_    1024
#define R_     8
#define G_     1024
#define WORDS  (B_ / 32)          // 256 batch words
#define OUTW   (W0_ + R_ * G_)    // 9216 output columns

// ---------------------------------------------------------------------------
// Fully fused kernel: one block per batch word (32 samples).
// The entire per-word column state (9216 uint32 = 36 KB) lives in shared
// memory. Phases:
//   1) pack:   x[w*32 .. w*32+31, 0..1023] -> ballot bits in smem
//   2) rows:   8 gate rows, all smem (LDS ~29cyc vs L2 ~240cyc), synced by
//              __syncthreads — replaces 8 separate kernel launches
//   3) unpack: smem bits -> out [B, OUTW] float32 via coalesced float4
//              streaming stores (write-once 302MB stream; bypass L2 fill)
// All 256 blocks are co-resident (36.9KB smem -> 6 blocks/SM cap), so the
// kernel runs as a single wave and is bounded by the HBM write stream.
// ---------------------------------------------------------------------------
__global__ __launch_bounds__(256) void gator_fused_kernel(
    const float* __restrict__ x,        // [B, W0] 0/1 floats
    const float* __restrict__ gates,    // [R, G, 4]
    const int*   __restrict__ choices,  // [R, G, 2]
    float*       __restrict__ out)      // [B, OUTW]
{
    __shared__ uint32_t s[OUTW];        // 36864 bytes

    const int w    = blockIdx.x;        // batch word (32 samples)
    const int tid  = threadIdx.x;
    const int warp = tid >> 5;
    const int lane = tid & 31;

    // ---- Phase 1: pack ---------------------------------------------------
    // Warp lane = sample; warp j covers columns [j*128, j*128+128).
    // Per-lane float4 loads stream sequentially through the sample's row, so
    // each 128B line fetched by a warp-load is reused 8x from L1.
    {
        const float4* row = reinterpret_cast<const float4*>(
            x + (size_t)(w * 32 + lane) * W0_);
        const int colbase = warp * 128;
        #pragma unroll 4
        for (int it = 0; it < 32; ++it) {
            const int c = colbase + it * 4;
            float4 v = row[c >> 2];
            uint32_t b0 = __ballot_sync(0xffffffffu, v.x > 0.5f);
            uint32_t b1 = __ballot_sync(0xffffffffu, v.y > 0.5f);
            uint32_t b2 = __ballot_sync(0xffffffffu, v.z > 0.5f);
            uint32_t b3 = __ballot_sync(0xffffffffu, v.w > 0.5f);
            if (lane == 0) {
                s[c + 0] = b0;
                s[c + 1] = b1;
                s[c + 2] = b2;
                s[c + 3] = b3;
            }
        }
    }
    __syncthreads();

    // ---- Phase 2: 8 gate rows in smem ------------------------------------
    // Thread t handles gates t, t+256, t+512, t+768 of each row: choices
    // (int2) and gates (float4) loads are coalesced and L2-hot (192KB shared
    // by all 256 blocks). Gate eval is pure bitwise LOP on 32 samples.
    #pragma unroll
    for (int r = 0; r < R_; ++r) {
        const float* gr = gates   + (size_t)r * G_ * 4;
        const int2*  cr = reinterpret_cast<const int2*>(choices) + (size_t)r * G_;
        const int outbase = W0_ + r * G_;

        #pragma unroll
        for (int k = 0; k < 4; ++k) {
            const int g = tid + k * 256;
            const int2 ch   = __ldg(cr + g);
            const float4 tt = __ldg(reinterpret_cast<const float4*>(gr + 4 * g));

            const uint32_t a  = s[ch.x];
            const uint32_t bb = s[ch.y];

            const uint32_t m0 = (tt.x > 0.5f) ? 0xffffffffu : 0u;  // (0,0)
            const uint32_t m1 = (tt.y > 0.5f) ? 0xffffffffu : 0u;  // (0,1)
            const uint32_t m2 = (tt.z > 0.5f) ? 0xffffffffu : 0u;  // (1,0)
            const uint32_t m3 = (tt.w > 0.5f) ? 0xffffffffu : 0u;  // (1,1)

            const uint32_t o = (m0 & ~a & ~bb) | (m1 & ~a & bb)
                             | (m2 &  a & ~bb) | (m3 &  a &  bb);

            s[outbase + g] = o;
        }
        __syncthreads();
    }

    // ---- Phase 3: unpack -------------------------------------------------
    // Thread owns 4 consecutive columns per pass (one LDS.128), expands the
    // 32 batch bits into 32 coalesced float4 streaming stores. Warp covers
    // 128 consecutive columns -> full 512B store transactions.
    #pragma unroll
    for (int p = 0; p < OUTW / 1024; ++p) {       // 9 passes
        const int c0 = p * 1024 + tid * 4;
        const uint4 bv = *reinterpret_cast<const uint4*>(&s[c0]);

        float* base = out + (size_t)(w * 32) * OUTW + c0;
        #pragma unroll
        for (int i = 0; i < 32; ++i) {
            float4 v;
            v.x = (float)((bv.x >> i) & 1u);
            v.y = (float)((bv.y >> i) & 1u);
            v.z = (float)((bv.z >> i) & 1u);
            v.w = (float)((bv.w >> i) & 1u);
            __stcs(reinterpret_cast<float4*>(base + (size_t)i * OUTW), v);
        }
    }
}

// ---------------------------------------------------------------------------
// Single launch; no allocation, no sync -> graph-capturable.
// Inputs (metadata order): x f32 [8192,1024], gates f32 [8,1024,4],
// choices i32 [8,1024,2]. Output f32 [8192, 9216].
// ---------------------------------------------------------------------------
extern "C" void kernel_launch(void* const* d_in, const int* in_sizes, int n_in,
                              void* d_out, int out_size) {
    const float* x       = (const float*)d_in[0];
    const float* gates   = (const float*)d_in[1];
    const int*   choices = (const int*)  d_in[2];
    float*       out     = (float*)d_out;

    gator_fused_kernel<<<WORDS, 256>>>(x, gates, choices, out);
}

// round 7
// speedup vs baseline: 1.3083x; 1.0078x over previous
#include <cuda_runtime.h>
#include <stdint.h>

// Problem constants (fixed by the reference)
#define B_     8192
#define W0_    1024
#define R_     8
#define G_     1024
#define WORDS  (B_ / 32)          // 256 batch words
#define OUTW   (W0_ + R_ * G_)    // 9216 output columns

// ---------------------------------------------------------------------------
// Fused kernel, store-interleaved: one block per batch word (32 samples).
// Per-word column state (9216 uint32 = 36 KB) lives in shared memory.
//
//   pack x -> smem bits
//   store cols [0,1024)               (starts the HBM write stream early)
//   for r = 0..7:
//       compute row r gates -> smem   (pure LOP3 on 32-sample words)
//       __syncthreads
//       store cols of row r           (fire-and-forget STG.128; next row's
//                                      compute proceeds underneath them)
//
// The 302 MB output stream is live for the whole kernel instead of bursting
// after all compute; pack reads and smem gate work hide under outstanding
// stores. One __syncthreads per row (compute writes region r+1, unpack reads
// region r, gathers read regions <= r: disjoint, no extra barrier needed).
// ---------------------------------------------------------------------------

// Unpack 1024 consecutive columns [c0base, c0base+1024) of batch word w from
// smem bits to out, as coalesced float4 streaming stores (write-once 302MB
// stream; keep it out of L2 fill).
__device__ __forceinline__ void unpack_1024(const uint32_t* __restrict__ s,
                                            float* __restrict__ out,
                                            int w, int c0base, int tid) {
    const int c0 = c0base + tid * 4;                     // 4 consecutive cols
    const uint4 bv = *reinterpret_cast<const uint4*>(&s[c0]);
    float* base = out + (size_t)(w * 32) * OUTW + c0;
    #pragma unroll
    for (int i = 0; i < 32; ++i) {
        float4 v;
        v.x = (float)((bv.x >> i) & 1u);
        v.y = (float)((bv.y >> i) & 1u);
        v.z = (float)((bv.z >> i) & 1u);
        v.w = (float)((bv.w >> i) & 1u);
        __stcs(reinterpret_cast<float4*>(base + (size_t)i * OUTW), v);
    }
}

__global__ __launch_bounds__(256) void gator_fused_kernel(
    const float* __restrict__ x,        // [B, W0] 0/1 floats
    const float* __restrict__ gates,    // [R, G, 4]
    const int*   __restrict__ choices,  // [R, G, 2]
    float*       __restrict__ out)      // [B, OUTW]
{
    __shared__ uint32_t s[OUTW];        // 36864 bytes

    const int w    = blockIdx.x;        // batch word (32 samples)
    const int tid  = threadIdx.x;
    const int warp = tid >> 5;
    const int lane = tid & 31;

    // ---- pack: x[w*32 .. w*32+31, :] -> ballot bits ----------------------
    // Warp lane = sample; warp j covers columns [j*128, j*128+128). Per-lane
    // float4 loads stream sequentially, so each 128B line gets 8x L1 reuse.
    {
        const float4* row = reinterpret_cast<const float4*>(
            x + (size_t)(w * 32 + lane) * W0_);
        const int colbase = warp * 128;
        #pragma unroll 4
        for (int it = 0; it < 32; ++it) {
            const int c = colbase + it * 4;
            float4 v = row[c >> 2];
            uint32_t b0 = __ballot_sync(0xffffffffu, v.x > 0.5f);
            uint32_t b1 = __ballot_sync(0xffffffffu, v.y > 0.5f);
            uint32_t b2 = __ballot_sync(0xffffffffu, v.z > 0.5f);
            uint32_t b3 = __ballot_sync(0xffffffffu, v.w > 0.5f);
            if (lane == 0) {
                s[c + 0] = b0;
                s[c + 1] = b1;
                s[c + 2] = b2;
                s[c + 3] = b3;
            }
        }
    }
    __syncthreads();

    // ---- start the output stream with the x columns ----------------------
    unpack_1024(s, out, w, 0, tid);

    // ---- 8 gate rows, each immediately followed by its store pass --------
    #pragma unroll
    for (int r = 0; r < R_; ++r) {
        const float* gr = gates   + (size_t)r * G_ * 4;
        const int2*  cr = reinterpret_cast<const int2*>(choices) + (size_t)r * G_;
        const int outbase = W0_ + r * G_;

        // Thread t handles gates t, t+256, t+512, t+768: int2/float4 param
        // loads coalesced and L2-hot (192KB total, shared by all 256 blocks).
        #pragma unroll
        for (int k = 0; k < 4; ++k) {
            const int g = tid + k * 256;
            const int2 ch   = __ldg(cr + g);
            const float4 tt = __ldg(reinterpret_cast<const float4*>(gr + 4 * g));

            const uint32_t a  = s[ch.x];
            const uint32_t bb = s[ch.y];

            const uint32_t m0 = (tt.x > 0.5f) ? 0xffffffffu : 0u;  // (0,0)
            const uint32_t m1 = (tt.y > 0.5f) ? 0xffffffffu : 0u;  // (0,1)
            const uint32_t m2 = (tt.z > 0.5f) ? 0xffffffffu : 0u;  // (1,0)
            const uint32_t m3 = (tt.w > 0.5f) ? 0xffffffffu : 0u;  // (1,1)

            const uint32_t o = (m0 & ~a & ~bb) | (m1 & ~a & bb)
                             | (m2 &  a & ~bb) | (m3 &  a &  bb);

            s[outbase + g] = o;
        }
        __syncthreads();

        // Stream out this row's columns; next iteration's compute writes a
        // disjoint smem region, so it runs under these stores with no extra
        // barrier.
        unpack_1024(s, out, w, outbase, tid);
    }
}

// ---------------------------------------------------------------------------
// Single launch; no allocation, no sync -> graph-capturable.
// Inputs (metadata order): x f32 [8192,1024], gates f32 [8,1024,4],
// choices i32 [8,1024,2]. Output f32 [8192, 9216].
// ---------------------------------------------------------------------------
extern "C" void kernel_launch(void* const* d_in, const int* in_sizes, int n_in,
                              void* d_out, int out_size) {
    const float* x       = (const float*)d_in[0];
    const float* gates   = (const float*)d_in[1];
    const int*   choices = (const int*)  d_in[2];
    float*       out     = (float*)d_out;

    gator_fused_kernel<<<WORDS, 256>>>(x, gates, choices, out);
}

// round 8
// speedup vs baseline: 1.3152x; 1.0052x over previous
#include <cuda_runtime.h>
#include <stdint.h>

// Problem constants (fixed by the reference)
#define B_     8192
#define W0_    1024
#define R_     8
#define G_     1024
#define WORDS  (B_ / 32)          // 256 batch words
#define OUTW   (W0_ + R_ * G_)    // 9216 output columns
#define NT     512                // threads per block

#define ONE_F  0x3F800000u        // bit pattern of 1.0f

// ---------------------------------------------------------------------------
// Fused kernel, 512 threads/block, one block per batch word (32 samples).
// Per-word column state (9216 uint32 = 36 KB) lives in shared memory.
//
//   pack x -> smem bits (ballot)
//   store cols [0,1024)
//   for r = 0..7: compute row r gates -> smem; __syncthreads; store row r
//
// R8 changes vs R7:
//   * 512 threads (occ 21.8% -> ~43%): store supply was the limiter
//     (DRAM 57.6% with issue 16.4% => latency-bound, not BW-bound).
//   * Unpack emits the float bit pattern with integer ALU only
//     (bit ? 0x3F800000 : 0) — removes 12 quarter-rate I2F per float4 store.
//   * Unpack splits each 1024-col region as (4 cols) x (16 rows) per thread:
//     shorter serial chains, identical 512B-coalesced STG.128.
// ---------------------------------------------------------------------------

// Store 1024 consecutive columns [c0base, c0base+1024) of batch word w.
// Threads 0..255 handle batch rows 0..15, threads 256..511 rows 16..31.
__device__ __forceinline__ void unpack_1024(const uint32_t* __restrict__ s,
                                            float* __restrict__ out,
                                            int w, int c0base, int tid) {
    const int half = tid >> 8;                 // 0 or 1
    const int t2   = tid & 255;
    const int c0   = c0base + t2 * 4;          // 4 consecutive cols
    const uint4 bv = *reinterpret_cast<const uint4*>(&s[c0]);

    uint32_t* base = reinterpret_cast<uint32_t*>(out)
                   + (size_t)(w * 32 + half * 16) * OUTW + c0;

    #pragma unroll
    for (int i = 0; i < 16; ++i) {
        const int bit = half * 16 + i;
        uint4 v;
        v.x = ((bv.x >> bit) & 1u) * ONE_F;    // SHF+LOP+IMAD, all fixed-lat
        v.y = ((bv.y >> bit) & 1u) * ONE_F;
        v.z = ((bv.z >> bit) & 1u) * ONE_F;
        v.w = ((bv.w >> bit) & 1u) * ONE_F;
        __stcs(reinterpret_cast<uint4*>(base + (size_t)i * OUTW), v);
    }
}

__global__ __launch_bounds__(NT) void gator_fused_kernel(
    const float* __restrict__ x,        // [B, W0] 0/1 floats
    const float* __restrict__ gates,    // [R, G, 4]
    const int*   __restrict__ choices,  // [R, G, 2]
    float*       __restrict__ out)      // [B, OUTW]
{
    __shared__ uint32_t s[OUTW];        // 36864 bytes

    const int w    = blockIdx.x;        // batch word (32 samples)
    const int tid  = threadIdx.x;
    const int warp = tid >> 5;          // 0..15
    const int lane = tid & 31;

    // ---- pack: x[w*32 .. w*32+31, :] -> ballot bits ----------------------
    // Lane = sample; warp j covers columns [j*64, j*64+64). Per-lane float4
    // loads stream sequentially -> 8x L1 reuse of each 128B line.
    {
        const float4* row = reinterpret_cast<const float4*>(
            x + (size_t)(w * 32 + lane) * W0_);
        const int colbase = warp * 64;
        #pragma unroll 4
        for (int it = 0; it < 16; ++it) {
            const int c = colbase + it * 4;
            float4 v = row[c >> 2];
            uint32_t b0 = __ballot_sync(0xffffffffu, v.x > 0.5f);
            uint32_t b1 = __ballot_sync(0xffffffffu, v.y > 0.5f);
            uint32_t b2 = __ballot_sync(0xffffffffu, v.z > 0.5f);
            uint32_t b3 = __ballot_sync(0xffffffffu, v.w > 0.5f);
            if (lane == 0) {
                s[c + 0] = b0;
                s[c + 1] = b1;
                s[c + 2] = b2;
                s[c + 3] = b3;
            }
        }
    }
    __syncthreads();

    // ---- start the output stream with the x columns ----------------------
    unpack_1024(s, out, w, 0, tid);

    // ---- 8 gate rows, each immediately followed by its store pass --------
    #pragma unroll
    for (int r = 0; r < R_; ++r) {
        const float* gr = gates   + (size_t)r * G_ * 4;
        const int2*  cr = reinterpret_cast<const int2*>(choices) + (size_t)r * G_;
        const int outbase = W0_ + r * G_;

        // Thread t handles gates t and t+512; param loads coalesced, L2-hot.
        #pragma unroll
        for (int k = 0; k < 2; ++k) {
            const int g = tid + k * NT;
            const int2 ch   = __ldg(cr + g);
            const float4 tt = __ldg(reinterpret_cast<const float4*>(gr + 4 * g));

            const uint32_t a  = s[ch.x];
            const uint32_t bb = s[ch.y];

            const uint32_t m0 = (tt.x > 0.5f) ? 0xffffffffu : 0u;  // (0,0)
            const uint32_t m1 = (tt.y > 0.5f) ? 0xffffffffu : 0u;  // (0,1)
            const uint32_t m2 = (tt.z > 0.5f) ? 0xffffffffu : 0u;  // (1,0)
            const uint32_t m3 = (tt.w > 0.5f) ? 0xffffffffu : 0u;  // (1,1)

            const uint32_t o = (m0 & ~a & ~bb) | (m1 & ~a & bb)
                             | (m2 &  a & ~bb) | (m3 &  a &  bb);

            s[outbase + g] = o;
        }
        __syncthreads();

        // Stream out this row; next row's compute (disjoint smem region)
        // runs under the outstanding stores with no extra barrier.
        unpack_1024(s, out, w, outbase, tid);
    }
}

// ---------------------------------------------------------------------------
// Single launch; no allocation, no sync -> graph-capturable.
// Inputs (metadata order): x f32 [8192,1024], gates f32 [8,1024,4],
// choices i32 [8,1024,2]. Output f32 [8192, 9216].
// ---------------------------------------------------------------------------
extern "C" void kernel_launch(void* const* d_in, const int* in_sizes, int n_in,
                              void* d_out, int out_size) {
    const float* x       = (const float*)d_in[0];
    const float* gates   = (const float*)d_in[1];
    const int*   choices = (const int*)  d_in[2];
    float*       out     = (float*)d_out;

    gator_fused_kernel<<<WORDS, NT>>>(x, gates, choices, out);
}